// round 1
// baseline (speedup 1.0000x reference)
#include <cuda_runtime.h>
#include <math.h>

#define NN   10000
#define EE   320000
#define DIN  128
#define DHID 128
#define DOUT 64

// ---------------- scratch (static __device__ globals: allocation-free) ----------------
__device__ float g_yrel [NN*DHID];   // x @ W_rel0
__device__ float g_yroot[NN*DHID];   // x @ W_root0 + b0
__device__ float g_agg0 [NN*DHID];   // scatter of g_yrel
__device__ float g_h    [NN*DHID];   // tanh(agg0 + yroot)
__device__ float g_u    [NN*DOUT];   // h @ W_rel1
__device__ float g_v    [NN*DOUT];   // h @ W_root1 + b1
__device__ float g_agg1 [NN*DOUT];   // scatter of g_u
__device__ float g_h2   [NN*DOUT];   // final embeddings
__device__ float g_hn   [NN*DOUT];   // normalized embeddings
__device__ int   g_pos  [2*EE];      // normalized int32 edge indices (src | dst)
__device__ int   g_neg  [2*EE];
__device__ float g_loss [2];         // {pos_sum, neg_sum}
__device__ int   g_is64;             // edge index dtype flag

// ---------------- dtype detect + index normalization ----------------
__global__ void detect_kernel(const void* p) {
    // If data is int64 (values < 2^31, nonneg), every high dword is 0.
    // If int32, the odd dwords are random node ids in [0,10000): P(all 64 zero) ~ 1e-256.
    const unsigned* u = (const unsigned*)p;
    int lane = threadIdx.x & 31;
    int nz = 0;
    for (int i = lane; i < 64; i += 32) nz |= (u[2*i + 1] != 0u);
    for (int off = 16; off; off >>= 1) nz |= __shfl_xor_sync(0xffffffffu, nz, off);
    if (lane == 0) g_is64 = !nz;
}

__global__ void convert_kernel(const void* p, int* dst) {
    int i = blockIdx.x * blockDim.x + threadIdx.x;
    if (i >= 2*EE) return;
    int v;
    if (g_is64) v = (int)((const long long*)p)[i];
    else        v = ((const int*)p)[i];
    dst[i] = v;
}

// ---------------- zero scratch ----------------
__global__ void zero_kernel() {
    int idx = blockIdx.x * blockDim.x + threadIdx.x;
    int stride = gridDim.x * blockDim.x;
    for (int i = idx; i < NN*DHID; i += stride) g_agg0[i] = 0.f;
    for (int i = idx; i < NN*DOUT; i += stride) g_agg1[i] = 0.f;
    if (idx < 2) g_loss[idx] = 0.f;
}

// ---------------- generic small SGEMM: C[M,Nc] = A[M,K] @ B[K,Nc] (+bias) ----------------
// BM=BN=64, BK=16, 256 threads, 4x4 micro-tile. K multiple of 16, Nc multiple of 64.
__global__ __launch_bounds__(256) void sgemm_kernel(
    const float* __restrict__ A, const float* __restrict__ B,
    const float* __restrict__ bias, float* __restrict__ C,
    int M, int K, int Nc)
{
    __shared__ float As[16][64];
    __shared__ float Bs[16][68];
    int tid = threadIdx.x;
    int br = blockIdx.y * 64, bc = blockIdx.x * 64;
    int m0 = (tid >> 4) * 4, n0 = (tid & 15) * 4;
    float acc[4][4] = {};
    for (int k0 = 0; k0 < K; k0 += 16) {
        for (int i = tid; i < 64*16; i += 256) {
            int r = i >> 4, c = i & 15;
            As[c][r] = (br + r < M) ? A[(size_t)(br + r) * K + k0 + c] : 0.f;
        }
        for (int i = tid; i < 16*64; i += 256) {
            int r = i >> 6, c = i & 63;
            Bs[r][c] = B[(size_t)(k0 + r) * Nc + bc + c];
        }
        __syncthreads();
        #pragma unroll
        for (int k = 0; k < 16; k++) {
            float a[4], b[4];
            #pragma unroll
            for (int i = 0; i < 4; i++) a[i] = As[k][m0 + i];
            #pragma unroll
            for (int j = 0; j < 4; j++) b[j] = Bs[k][n0 + j];
            #pragma unroll
            for (int i = 0; i < 4; i++)
                #pragma unroll
                for (int j = 0; j < 4; j++)
                    acc[i][j] += a[i] * b[j];
        }
        __syncthreads();
    }
    #pragma unroll
    for (int i = 0; i < 4; i++) {
        int r = br + m0 + i;
        if (r >= M) continue;
        #pragma unroll
        for (int j = 0; j < 4; j++) {
            float bv = bias ? bias[bc + n0 + j] : 0.f;
            C[(size_t)r * Nc + bc + n0 + j] = acc[i][j] + bv;
        }
    }
}

// ---------------- scatter-add (segment_sum) ----------------
template<int D>
__global__ void scatter_kernel(const float* __restrict__ feat,
                               const int* __restrict__ ei,
                               float* __restrict__ agg)
{
    const int D4 = D / 4;
    int idx = blockIdx.x * blockDim.x + threadIdx.x;
    if (idx >= EE * D4) return;
    int e = idx / D4;
    int f = (idx % D4) * 4;
    int s = ei[e];
    int d = ei[EE + e];
    float4 v = *(const float4*)&feat[(size_t)s * D + f];
    float* base = &agg[(size_t)d * D + f];
    atomicAdd(base + 0, v.x);
    atomicAdd(base + 1, v.y);
    atomicAdd(base + 2, v.z);
    atomicAdd(base + 3, v.w);
}

// ---------------- h = tanh(agg0 + yroot) ----------------
__global__ void tanh_add_kernel() {
    int i = blockIdx.x * blockDim.x + threadIdx.x;
    if (i < NN*DHID) g_h[i] = tanhf(g_agg0[i] + g_yroot[i]);
}

// ---------------- h2 = agg1 + v; hn = h2 / max(||h2||, 1e-8) ----------------
__global__ void finalize_kernel() {
    int warp = (blockIdx.x * blockDim.x + threadIdx.x) >> 5;
    int lane = threadIdx.x & 31;
    if (warp >= NN) return;
    int base = warp * DOUT + lane * 2;
    float2 a = *(const float2*)&g_agg1[base];
    float2 b = *(const float2*)&g_v[base];
    float x0 = a.x + b.x, x1 = a.y + b.y;
    float ss = x0*x0 + x1*x1;
    for (int off = 16; off; off >>= 1) ss += __shfl_xor_sync(0xffffffffu, ss, off);
    float inv = 1.f / fmaxf(sqrtf(ss), 1e-8f);
    *(float2*)&g_h2[base] = make_float2(x0, x1);
    *(float2*)&g_hn[base] = make_float2(x0*inv, x1*inv);
}

// ---------------- BCE reconstruction loss ----------------
__global__ __launch_bounds__(512) void loss_kernel() {
    __shared__ float s_acc[2];
    if (threadIdx.x < 2) s_acc[threadIdx.x] = 0.f;
    __syncthreads();
    int gw = (blockIdx.x * blockDim.x + threadIdx.x) >> 5;
    int lane = threadIdx.x & 31;
    if (gw < 2*EE) {
        int isneg = (gw >= EE) ? 1 : 0;
        const int* ei = isneg ? g_neg : g_pos;
        int e = isneg ? gw - EE : gw;
        int s = ei[e], d = ei[EE + e];
        float2 a = *(const float2*)&g_h2[s * DOUT + lane * 2];
        float2 b = *(const float2*)&g_h2[d * DOUT + lane * 2];
        float dot = a.x*b.x + a.y*b.y;
        for (int off = 16; off; off >>= 1) dot += __shfl_xor_sync(0xffffffffu, dot, off);
        if (lane == 0) {
            float xx = isneg ? dot : -dot;   // pos: softplus(-score); neg: softplus(+score)
            float sp = (xx > 0.f) ? xx + log1pf(expf(-xx)) : log1pf(expf(xx));
            atomicAdd(&s_acc[isneg], sp);
        }
    }
    __syncthreads();
    if (threadIdx.x < 2) atomicAdd(&g_loss[threadIdx.x], s_acc[threadIdx.x]);
}

__global__ void write_loss_kernel(float* out) {
    out[(size_t)NN * NN] = g_loss[0] * (1.f / EE) + g_loss[1] * (1.f / EE);
}

// ---------------- sim = sigmoid(hn @ hn^T): 128x128 tile, K=64, 8x8 microtile ----------------
// Shared layout: As/Bs stored [k][m] with pad 132 (conflict-free f4 loads, 16B aligned rows).
#define SIM_PAD 132
__global__ __launch_bounds__(256, 2) void sim_kernel(float* __restrict__ out) {
    extern __shared__ float sm[];
    float* As = sm;                 // [64][132]
    float* Bs = sm + 64 * SIM_PAD;  // [64][132]
    int tid = threadIdx.x;
    int bi = blockIdx.y * 128, bj = blockIdx.x * 128;

    for (int i = tid; i < 128 * 16; i += 256) {
        int r = i >> 4, c = (i & 15) * 4;
        float4 va = (bi + r < NN) ? *(const float4*)&g_hn[(size_t)(bi + r) * DOUT + c]
                                  : make_float4(0.f, 0.f, 0.f, 0.f);
        As[(c + 0) * SIM_PAD + r] = va.x;
        As[(c + 1) * SIM_PAD + r] = va.y;
        As[(c + 2) * SIM_PAD + r] = va.z;
        As[(c + 3) * SIM_PAD + r] = va.w;
        float4 vb = (bj + r < NN) ? *(const float4*)&g_hn[(size_t)(bj + r) * DOUT + c]
                                  : make_float4(0.f, 0.f, 0.f, 0.f);
        Bs[(c + 0) * SIM_PAD + r] = vb.x;
        Bs[(c + 1) * SIM_PAD + r] = vb.y;
        Bs[(c + 2) * SIM_PAD + r] = vb.z;
        Bs[(c + 3) * SIM_PAD + r] = vb.w;
    }
    __syncthreads();

    int m0 = (tid >> 4) * 8, n0 = (tid & 15) * 8;
    float acc[8][8];
    #pragma unroll
    for (int i = 0; i < 8; i++)
        #pragma unroll
        for (int j = 0; j < 8; j++) acc[i][j] = 0.f;

    #pragma unroll 4
    for (int k = 0; k < 64; k++) {
        float4 a0 = *(const float4*)&As[k * SIM_PAD + m0];
        float4 a1 = *(const float4*)&As[k * SIM_PAD + m0 + 4];
        float4 b0 = *(const float4*)&Bs[k * SIM_PAD + n0];
        float4 b1 = *(const float4*)&Bs[k * SIM_PAD + n0 + 4];
        float a[8] = {a0.x, a0.y, a0.z, a0.w, a1.x, a1.y, a1.z, a1.w};
        float b[8] = {b0.x, b0.y, b0.z, b0.w, b1.x, b1.y, b1.z, b1.w};
        #pragma unroll
        for (int i = 0; i < 8; i++)
            #pragma unroll
            for (int j = 0; j < 8; j++)
                acc[i][j] += a[i] * b[j];
    }

    #pragma unroll
    for (int i = 0; i < 8; i++) {
        int r = bi + m0 + i;
        if (r >= NN) break;
        size_t rowoff = (size_t)r * NN + bj + n0;
        #pragma unroll
        for (int j = 0; j < 8; j++) {
            int c = bj + n0 + j;
            if (c >= NN) break;
            out[rowoff + j] = 1.f / (1.f + expf(-acc[i][j]));
        }
    }
}

// ---------------- launcher ----------------
extern "C" void kernel_launch(void* const* d_in, const int* in_sizes, int n_in,
                              void* d_out, int out_size)
{
    const float* x      = (const float*)d_in[1];
    const void*  ei_raw = d_in[2];
    const void*  ne_raw = d_in[3];
    const float* Wrel0  = (const float*)d_in[4];
    const float* Wroot0 = (const float*)d_in[5];
    const float* b0     = (const float*)d_in[6];
    const float* Wrel1  = (const float*)d_in[7];
    const float* Wroot1 = (const float*)d_in[8];
    const float* b1     = (const float*)d_in[9];
    float* out = (float*)d_out;

    float *yrel, *yroot, *agg0, *h, *u, *v;
    int *pos, *neg;
    cudaGetSymbolAddress((void**)&yrel,  g_yrel);
    cudaGetSymbolAddress((void**)&yroot, g_yroot);
    cudaGetSymbolAddress((void**)&agg0,  g_agg0);
    cudaGetSymbolAddress((void**)&h,     g_h);
    cudaGetSymbolAddress((void**)&u,     g_u);
    cudaGetSymbolAddress((void**)&v,     g_v);
    float* agg1; cudaGetSymbolAddress((void**)&agg1, g_agg1);
    cudaGetSymbolAddress((void**)&pos,   g_pos);
    cudaGetSymbolAddress((void**)&neg,   g_neg);

    const int smem_sim = 2 * 64 * SIM_PAD * sizeof(float);
    cudaFuncSetAttribute(sim_kernel, cudaFuncAttributeMaxDynamicSharedMemorySize, smem_sim);

    // dtype normalize + zero scratch
    detect_kernel<<<1, 32>>>(ei_raw);
    convert_kernel<<<(2*EE + 255) / 256, 256>>>(ei_raw, pos);
    convert_kernel<<<(2*EE + 255) / 256, 256>>>(ne_raw, neg);
    zero_kernel<<<2048, 256>>>();

    // layer 0
    sgemm_kernel<<<dim3(DHID/64, (NN + 63)/64), 256>>>(x, Wrel0,  nullptr, yrel,  NN, DIN, DHID);
    sgemm_kernel<<<dim3(DHID/64, (NN + 63)/64), 256>>>(x, Wroot0, b0,      yroot, NN, DIN, DHID);
    scatter_kernel<DHID><<<(EE * (DHID/4) + 255) / 256, 256>>>(yrel, pos, agg0);
    tanh_add_kernel<<<(NN*DHID + 255) / 256, 256>>>();

    // layer 1
    sgemm_kernel<<<dim3(DOUT/64, (NN + 63)/64), 256>>>(h, Wrel1,  nullptr, u, NN, DHID, DOUT);
    sgemm_kernel<<<dim3(DOUT/64, (NN + 63)/64), 256>>>(h, Wroot1, b1,      v, NN, DHID, DOUT);
    scatter_kernel<DOUT><<<(EE * (DOUT/4) + 255) / 256, 256>>>(u, pos, agg1);
    finalize_kernel<<<(NN + 7) / 8, 256>>>();

    // loss
    loss_kernel<<<(2*EE + 15) / 16, 512>>>();
    if ((long long)out_size > (long long)NN * NN)
        write_loss_kernel<<<1, 1>>>(out);

    // dense sigmoid(hn @ hn^T)
    dim3 simgrid((NN + 127) / 128, (NN + 127) / 128);
    sim_kernel<<<simgrid, 256, smem_sim>>>(out);
}

// round 4
// speedup vs baseline: 1.8696x; 1.8696x over previous
#include <cuda_runtime.h>
#include <cuda_bf16.h>
#include <mma.h>
#include <math.h>

using namespace nvcuda;

#define NN   10000
#define NPAD 10112          // 79 * 128
#define EE   320000
#define DIN  128
#define DHID 128
#define DOUT 64

// ---------------- scratch (static __device__ globals: allocation-free) ----------------
__device__ float g_yrel [NN*DHID];   // x @ W_rel0
__device__ float g_yroot[NN*DHID];   // x @ W_root0 + b0
__device__ float g_agg0 [NN*DHID];   // scatter of g_yrel
__device__ float g_h    [NN*DHID];   // tanh(agg0 + yroot)
__device__ float g_u    [NN*DOUT];   // h @ W_rel1
__device__ float g_v    [NN*DOUT];   // h @ W_root1 + b1
__device__ float g_agg1 [NN*DOUT];   // scatter of g_u
__device__ float g_h2   [NN*DOUT];   // final embeddings
__device__ __nv_bfloat16 g_hhi[NPAD*DOUT];  // bf16 hi part of normalized h (pad rows stay 0)
__device__ __nv_bfloat16 g_hlo[NPAD*DOUT];  // bf16 lo part
__device__ int   g_pos  [2*EE];      // normalized int32 edge indices (src | dst)
__device__ int   g_neg  [2*EE];
__device__ float g_loss [2];         // {pos_sum, neg_sum}
__device__ int   g_is64;             // edge index dtype flag

// ---------------- MUFU-free sigmoid for |x| <= ~1.01 ----------------
// sigmoid(x) = 0.5 + 0.5*tanh(x/2); odd Taylor of tanh to u^13, |u|<=0.5 -> err ~4e-8
__device__ __forceinline__ float sigmoid_poly(float x) {
    float u  = 0.5f * x;
    float u2 = u * u;
    float p = 3.5921279e-3f;
    p = fmaf(p, u2, -8.8632355e-3f);
    p = fmaf(p, u2,  2.1869488e-2f);
    p = fmaf(p, u2, -5.3968254e-2f);
    p = fmaf(p, u2,  1.3333334e-1f);
    p = fmaf(p, u2, -3.3333334e-1f);
    p = fmaf(p, u2,  1.0f);
    float t = u * p;                  // tanh(x/2)
    return fmaf(0.5f, t, 0.5f);
}

// ---------------- dtype detect + index normalization ----------------
__global__ void detect_kernel(const void* p) {
    const unsigned* u = (const unsigned*)p;
    int lane = threadIdx.x & 31;
    int nz = 0;
    for (int i = lane; i < 64; i += 32) nz |= (u[2*i + 1] != 0u);
    for (int off = 16; off; off >>= 1) nz |= __shfl_xor_sync(0xffffffffu, nz, off);
    if (lane == 0) g_is64 = !nz;
}

__global__ void convert_kernel(const void* p0, const void* p1) {
    int i = blockIdx.x * blockDim.x + threadIdx.x;
    if (i >= 2*EE) return;
    if (g_is64) {
        g_pos[i] = (int)((const long long*)p0)[i];
        g_neg[i] = (int)((const long long*)p1)[i];
    } else {
        g_pos[i] = ((const int*)p0)[i];
        g_neg[i] = ((const int*)p1)[i];
    }
}

// ---------------- zero scratch ----------------
__global__ void zero_kernel() {
    int idx = blockIdx.x * blockDim.x + threadIdx.x;
    int stride = gridDim.x * blockDim.x;
    for (int i = idx; i < NN*DHID; i += stride) g_agg0[i] = 0.f;
    for (int i = idx; i < NN*DOUT; i += stride) g_agg1[i] = 0.f;
    if (idx < 2) g_loss[idx] = 0.f;
}

// ---------------- generic small SGEMM: C[M,Nc] = A[M,K] @ B[K,Nc] (+bias) ----------------
__global__ __launch_bounds__(256) void sgemm_kernel(
    const float* __restrict__ A, const float* __restrict__ B,
    const float* __restrict__ bias, float* __restrict__ C,
    int M, int K, int Nc)
{
    __shared__ float As[16][64];
    __shared__ float Bs[16][68];
    int tid = threadIdx.x;
    int br = blockIdx.y * 64, bc = blockIdx.x * 64;
    int m0 = (tid >> 4) * 4, n0 = (tid & 15) * 4;
    float acc[4][4] = {};
    for (int k0 = 0; k0 < K; k0 += 16) {
        for (int i = tid; i < 64*16; i += 256) {
            int r = i >> 4, c = i & 15;
            As[c][r] = (br + r < M) ? A[(size_t)(br + r) * K + k0 + c] : 0.f;
        }
        for (int i = tid; i < 16*64; i += 256) {
            int r = i >> 6, c = i & 63;
            Bs[r][c] = B[(size_t)(k0 + r) * Nc + bc + c];
        }
        __syncthreads();
        #pragma unroll
        for (int k = 0; k < 16; k++) {
            float a[4], b[4];
            #pragma unroll
            for (int i = 0; i < 4; i++) a[i] = As[k][m0 + i];
            #pragma unroll
            for (int j = 0; j < 4; j++) b[j] = Bs[k][n0 + j];
            #pragma unroll
            for (int i = 0; i < 4; i++)
                #pragma unroll
                for (int j = 0; j < 4; j++)
                    acc[i][j] += a[i] * b[j];
        }
        __syncthreads();
    }
    #pragma unroll
    for (int i = 0; i < 4; i++) {
        int r = br + m0 + i;
        if (r >= M) continue;
        #pragma unroll
        for (int j = 0; j < 4; j++) {
            float bv = bias ? bias[bc + n0 + j] : 0.f;
            C[(size_t)r * Nc + bc + n0 + j] = acc[i][j] + bv;
        }
    }
}

// ---------------- scatter-add (segment_sum), scalar atomics (R1-proven path) ----------------
template<int D>
__global__ void scatter_kernel(const float* __restrict__ feat,
                               const int* __restrict__ ei,
                               float* __restrict__ agg)
{
    const int D4 = D / 4;
    int idx = blockIdx.x * blockDim.x + threadIdx.x;
    if (idx >= EE * D4) return;
    int e = idx / D4;
    int f = (idx % D4) * 4;
    int s = ei[e];
    int d = ei[EE + e];
    float4 v = *(const float4*)&feat[(size_t)s * D + f];
    float* base = &agg[(size_t)d * D + f];
    atomicAdd(base + 0, v.x);
    atomicAdd(base + 1, v.y);
    atomicAdd(base + 2, v.z);
    atomicAdd(base + 3, v.w);
}

// ---------------- h = tanh(agg0 + yroot) ----------------
__global__ void tanh_add_kernel() {
    int i = blockIdx.x * blockDim.x + threadIdx.x;
    if (i < NN*DHID) g_h[i] = tanhf(g_agg0[i] + g_yroot[i]);
}

// ---------------- h2 = agg1 + v; hi/lo bf16 split of h2/max(||h2||,1e-8) ----------------
__global__ void finalize_kernel() {
    int warp = (blockIdx.x * blockDim.x + threadIdx.x) >> 5;
    int lane = threadIdx.x & 31;
    if (warp >= NN) return;
    int base = warp * DOUT + lane * 2;
    float2 a = *(const float2*)&g_agg1[base];
    float2 b = *(const float2*)&g_v[base];
    float x0 = a.x + b.x, x1 = a.y + b.y;
    float ss = x0*x0 + x1*x1;
    for (int off = 16; off; off >>= 1) ss += __shfl_xor_sync(0xffffffffu, ss, off);
    float inv = 1.f / fmaxf(sqrtf(ss), 1e-8f);
    *(float2*)&g_h2[base] = make_float2(x0, x1);
    float n0 = x0 * inv, n1 = x1 * inv;
    __nv_bfloat16 h0 = __float2bfloat16(n0);
    __nv_bfloat16 h1 = __float2bfloat16(n1);
    __nv_bfloat16 l0 = __float2bfloat16(n0 - __bfloat162float(h0));
    __nv_bfloat16 l1 = __float2bfloat16(n1 - __bfloat162float(h1));
    *(__nv_bfloat162*)&g_hhi[base] = __halves2bfloat162(h0, h1);
    *(__nv_bfloat162*)&g_hlo[base] = __halves2bfloat162(l0, l1);
}

// ---------------- BCE reconstruction loss ----------------
__global__ __launch_bounds__(512) void loss_kernel() {
    __shared__ float s_acc[2];
    if (threadIdx.x < 2) s_acc[threadIdx.x] = 0.f;
    __syncthreads();
    int gw = (blockIdx.x * blockDim.x + threadIdx.x) >> 5;
    int lane = threadIdx.x & 31;
    if (gw < 2*EE) {
        int isneg = (gw >= EE) ? 1 : 0;
        const int* ei = isneg ? g_neg : g_pos;
        int e = isneg ? gw - EE : gw;
        int s = ei[e], d = ei[EE + e];
        float2 a = *(const float2*)&g_h2[s * DOUT + lane * 2];
        float2 b = *(const float2*)&g_h2[d * DOUT + lane * 2];
        float dot = a.x*b.x + a.y*b.y;
        for (int off = 16; off; off >>= 1) dot += __shfl_xor_sync(0xffffffffu, dot, off);
        if (lane == 0) {
            float xx = isneg ? dot : -dot;
            float sp = (xx > 0.f) ? xx + log1pf(expf(-xx)) : log1pf(expf(xx));
            atomicAdd(&s_acc[isneg], sp);
        }
    }
    __syncthreads();
    if (threadIdx.x < 2) atomicAdd(&g_loss[threadIdx.x], s_acc[threadIdx.x]);
}

__global__ void write_loss_kernel(float* out) {
    out[(size_t)NN * NN] = g_loss[0] * (1.f / EE) + g_loss[1] * (1.f / EE);
}

// ---------------- sim = sigmoid(hn @ hn^T) via WMMA bf16 split-precision ----------------
// 128x128 tile / block, 512 threads (16 warps, 4x4), warp tile 32x32.
// Shared tiles padded to 72 bf16 per row (144B stride -> conflict-free LDSM phases).
#define LDA 72
#define STG_LD 132
__global__ __launch_bounds__(512) void sim_kernel(float* __restrict__ out) {
    extern __shared__ char smraw[];
    __nv_bfloat16* Ahi = (__nv_bfloat16*)smraw;
    __nv_bfloat16* Alo = Ahi + 128 * LDA;
    __nv_bfloat16* Bhi = Alo + 128 * LDA;
    __nv_bfloat16* Blo = Bhi + 128 * LDA;

    int tid = threadIdx.x;
    int bi = blockIdx.y * 128, bj = blockIdx.x * 128;

    // load tiles: 128 rows x 64 bf16 = 8 x int4 per row, for 4 tiles
    for (int i = tid; i < 128 * 8; i += 512) {
        int r = i >> 3, c = (i & 7) * 8;
        *(int4*)&Ahi[r * LDA + c] = *(const int4*)&g_hhi[(size_t)(bi + r) * DOUT + c];
        *(int4*)&Alo[r * LDA + c] = *(const int4*)&g_hlo[(size_t)(bi + r) * DOUT + c];
        *(int4*)&Bhi[r * LDA + c] = *(const int4*)&g_hhi[(size_t)(bj + r) * DOUT + c];
        *(int4*)&Blo[r * LDA + c] = *(const int4*)&g_hlo[(size_t)(bj + r) * DOUT + c];
    }
    __syncthreads();

    int warp = tid >> 5;
    int wm = (warp >> 2) * 32;   // warp row base in tile
    int wn = (warp & 3) * 32;    // warp col base in tile

    wmma::fragment<wmma::accumulator, 16, 16, 16, float> acc[2][2];
    #pragma unroll
    for (int i = 0; i < 2; i++)
        #pragma unroll
        for (int j = 0; j < 2; j++) wmma::fill_fragment(acc[i][j], 0.f);

    #pragma unroll
    for (int k0 = 0; k0 < 4; k0++) {
        wmma::fragment<wmma::matrix_a, 16, 16, 16, __nv_bfloat16, wmma::row_major> ahi[2], alo[2];
        wmma::fragment<wmma::matrix_b, 16, 16, 16, __nv_bfloat16, wmma::col_major> bhi[2], blo[2];
        #pragma unroll
        for (int i = 0; i < 2; i++) {
            wmma::load_matrix_sync(ahi[i], &Ahi[(wm + i*16) * LDA + k0*16], LDA);
            wmma::load_matrix_sync(alo[i], &Alo[(wm + i*16) * LDA + k0*16], LDA);
        }
        #pragma unroll
        for (int j = 0; j < 2; j++) {
            wmma::load_matrix_sync(bhi[j], &Bhi[(wn + j*16) * LDA + k0*16], LDA);
            wmma::load_matrix_sync(blo[j], &Blo[(wn + j*16) * LDA + k0*16], LDA);
        }
        #pragma unroll
        for (int i = 0; i < 2; i++)
            #pragma unroll
            for (int j = 0; j < 2; j++) {
                wmma::mma_sync(acc[i][j], ahi[i], bhi[j], acc[i][j]);
                wmma::mma_sync(acc[i][j], ahi[i], blo[j], acc[i][j]);
                wmma::mma_sync(acc[i][j], alo[i], bhi[j], acc[i][j]);
            }
    }

    // sigmoid on accumulator elements (MUFU-free)
    #pragma unroll
    for (int i = 0; i < 2; i++)
        #pragma unroll
        for (int j = 0; j < 2; j++)
            #pragma unroll
            for (int e = 0; e < acc[i][j].num_elements; e++)
                acc[i][j].x[e] = sigmoid_poly(acc[i][j].x[e]);

    bool interior = (bi + 128 <= NN) && (bj + 128 <= NN);
    if (interior) {
        #pragma unroll
        for (int i = 0; i < 2; i++)
            #pragma unroll
            for (int j = 0; j < 2; j++)
                wmma::store_matrix_sync(&out[(size_t)(bi + wm + i*16) * NN + bj + wn + j*16],
                                        acc[i][j], NN, wmma::mem_row_major);
    } else {
        // stage in smem, then guarded copy
        __syncthreads();
        float* st = (float*)smraw;   // 128 x STG_LD
        #pragma unroll
        for (int i = 0; i < 2; i++)
            #pragma unroll
            for (int j = 0; j < 2; j++)
                wmma::store_matrix_sync(&st[(wm + i*16) * STG_LD + wn + j*16],
                                        acc[i][j], STG_LD, wmma::mem_row_major);
        __syncthreads();
        for (int i = tid; i < 128 * 128; i += 512) {
            int r = i >> 7, c = i & 127;
            if (bi + r < NN && bj + c < NN)
                out[(size_t)(bi + r) * NN + bj + c] = st[r * STG_LD + c];
        }
    }
}

// ---------------- launcher ----------------
extern "C" void kernel_launch(void* const* d_in, const int* in_sizes, int n_in,
                              void* d_out, int out_size)
{
    const float* x      = (const float*)d_in[1];
    const void*  ei_raw = d_in[2];
    const void*  ne_raw = d_in[3];
    const float* Wrel0  = (const float*)d_in[4];
    const float* Wroot0 = (const float*)d_in[5];
    const float* b0     = (const float*)d_in[6];
    const float* Wrel1  = (const float*)d_in[7];
    const float* Wroot1 = (const float*)d_in[8];
    const float* b1     = (const float*)d_in[9];
    float* out = (float*)d_out;

    float *yrel, *yroot, *agg0, *h, *u, *v, *agg1;
    int *pos;
    cudaGetSymbolAddress((void**)&yrel,  g_yrel);
    cudaGetSymbolAddress((void**)&yroot, g_yroot);
    cudaGetSymbolAddress((void**)&agg0,  g_agg0);
    cudaGetSymbolAddress((void**)&h,     g_h);
    cudaGetSymbolAddress((void**)&u,     g_u);
    cudaGetSymbolAddress((void**)&v,     g_v);
    cudaGetSymbolAddress((void**)&agg1,  g_agg1);
    cudaGetSymbolAddress((void**)&pos,   g_pos);

    const int smem_sim = 4 * 128 * LDA * (int)sizeof(__nv_bfloat16);  // 73728
    cudaFuncSetAttribute(sim_kernel, cudaFuncAttributeMaxDynamicSharedMemorySize, smem_sim);

    // dtype normalize + zero scratch
    detect_kernel<<<1, 32>>>(ei_raw);
    convert_kernel<<<(2*EE + 255) / 256, 256>>>(ei_raw, ne_raw);
    zero_kernel<<<2048, 256>>>();

    // layer 0
    sgemm_kernel<<<dim3(DHID/64, (NN + 63)/64), 256>>>(x, Wrel0,  nullptr, yrel,  NN, DIN, DHID);
    sgemm_kernel<<<dim3(DHID/64, (NN + 63)/64), 256>>>(x, Wroot0, b0,      yroot, NN, DIN, DHID);
    scatter_kernel<DHID><<<(EE * (DHID/4) + 255) / 256, 256>>>(yrel, pos, agg0);
    tanh_add_kernel<<<(NN*DHID + 255) / 256, 256>>>();

    // layer 1
    sgemm_kernel<<<dim3(DOUT/64, (NN + 63)/64), 256>>>(h, Wrel1,  nullptr, u, NN, DHID, DOUT);
    sgemm_kernel<<<dim3(DOUT/64, (NN + 63)/64), 256>>>(h, Wroot1, b1,      v, NN, DHID, DOUT);
    scatter_kernel<DOUT><<<(EE * (DOUT/4) + 255) / 256, 256>>>(u, pos, agg1);
    finalize_kernel<<<(NN + 7) / 8, 256>>>();

    // loss
    loss_kernel<<<(2*EE + 15) / 16, 512>>>();
    if ((long long)out_size > (long long)NN * NN)
        write_loss_kernel<<<1, 1>>>(out);

    // dense sigmoid(hn @ hn^T)
    dim3 simgrid((NN + 127) / 128, (NN + 127) / 128);
    sim_kernel<<<simgrid, 512, smem_sim>>>(out);
}

// round 5
// speedup vs baseline: 2.7088x; 1.4488x over previous
#include <cuda_runtime.h>
#include <cuda_bf16.h>
#include <mma.h>
#include <math.h>

using namespace nvcuda;

#define NN   10000
#define NPAD 10112          // 79 * 128
#define EE   320000
#define DIN  128
#define DHID 128
#define DOUT 64

// ---------------- scratch (static __device__ globals: allocation-free) ----------------
__device__ __nv_bfloat16 g_xhi[NN*DIN];     // bf16 hi/lo split of x
__device__ __nv_bfloat16 g_xlo[NN*DIN];
__device__ __nv_bfloat16 g_B0hi[DIN*256];   // [Wrel0 | Wroot0] split
__device__ __nv_bfloat16 g_B0lo[DIN*256];
__device__ __nv_bfloat16 g_B1hi[DHID*128];  // [Wrel1 | Wroot1] split
__device__ __nv_bfloat16 g_B1lo[DHID*128];
__device__ float g_y0 [NN*256];             // [x@Wrel0 | x@Wroot0]
__device__ float g_y1 [NN*128];             // [h@Wrel1 | h@Wroot1]
__device__ __nv_bfloat16 g_hh0[NN*DHID];    // split of h (layer-1 A input)
__device__ __nv_bfloat16 g_hl0[NN*DHID];
__device__ float g_h2 [NN*DOUT];            // final embeddings
__device__ __nv_bfloat16 g_hhi[NPAD*DOUT];  // split of normalized h (pad rows stay 0)
__device__ __nv_bfloat16 g_hlo[NPAD*DOUT];
__device__ int   g_pos  [2*EE];             // int32 edge indices (src | dst)
__device__ int   g_neg  [2*EE];
__device__ int   g_deg  [NN];               // CSR build
__device__ int   g_off  [NN+1];
__device__ int   g_cursor[NN];
__device__ int   g_srcs [EE];               // srcs grouped by dst
__device__ float g_loss [2];
__device__ int   g_is64;

// ---------------- MUFU-free sigmoid for |x| <= ~1.01 ----------------
// sigmoid(x) = 0.5 + 0.5*tanh(x/2); odd Taylor of tanh to u^9, |u|<=0.5 -> err ~4e-6
__device__ __forceinline__ float sigmoid_poly(float x) {
    float u  = 0.5f * x;
    float u2 = u * u;
    float p = 2.1869488e-2f;          //  62/2835
    p = fmaf(p, u2, -5.3968254e-2f);  // -17/315
    p = fmaf(p, u2,  1.3333334e-1f);  //  2/15
    p = fmaf(p, u2, -3.3333334e-1f);  // -1/3
    p = fmaf(p, u2,  1.0f);
    return fmaf(0.5f, u * p, 0.5f);
}

__device__ __forceinline__ void split_bf16(float v, __nv_bfloat16& hi, __nv_bfloat16& lo) {
    hi = __float2bfloat16(v);
    lo = __float2bfloat16(v - __bfloat162float(hi));
}

// ---------------- dtype detect ----------------
__global__ void detect_kernel(const void* p) {
    const unsigned* u = (const unsigned*)p;
    int lane = threadIdx.x & 31;
    int nz = 0;
    for (int i = lane; i < 64; i += 32) nz |= (u[2*i + 1] != 0u);
    for (int off = 16; off; off >>= 1) nz |= __shfl_xor_sync(0xffffffffu, nz, off);
    if (lane == 0) g_is64 = !nz;
}

// ---------------- zero deg + loss ----------------
__global__ void init_kernel() {
    int i = blockIdx.x * blockDim.x + threadIdx.x;
    if (i < NN) g_deg[i] = 0;
    if (i < 2)  g_loss[i] = 0.f;
}

// ---------------- edge convert + degree count ----------------
__global__ void convert_kernel(const void* p0, const void* p1) {
    int i = blockIdx.x * blockDim.x + threadIdx.x;
    if (i >= 2*EE) return;
    int vp, vn;
    if (g_is64) {
        vp = (int)((const long long*)p0)[i];
        vn = (int)((const long long*)p1)[i];
    } else {
        vp = ((const int*)p0)[i];
        vn = ((const int*)p1)[i];
    }
    g_pos[i] = vp;
    g_neg[i] = vn;
    if (i >= EE) atomicAdd(&g_deg[vp], 1);   // dst entries
}

// ---------------- exclusive scan of degrees (1 block) ----------------
__global__ __launch_bounds__(1024) void scan_kernel() {
    __shared__ int warp_sums[32];
    __shared__ int s_carry;
    int tid = threadIdx.x;
    if (tid == 0) s_carry = 0;
    __syncthreads();
    for (int base = 0; base < NN; base += 1024) {
        int i = base + tid;
        int v = (i < NN) ? g_deg[i] : 0;
        int x = v;
        #pragma unroll
        for (int off = 1; off < 32; off <<= 1) {
            int y = __shfl_up_sync(0xffffffffu, x, off);
            if ((tid & 31) >= off) x += y;
        }
        if ((tid & 31) == 31) warp_sums[tid >> 5] = x;
        __syncthreads();
        if (tid < 32) {
            int w = warp_sums[tid];
            int xs = w;
            #pragma unroll
            for (int off = 1; off < 32; off <<= 1) {
                int y = __shfl_up_sync(0xffffffffu, xs, off);
                if (tid >= off) xs += y;
            }
            warp_sums[tid] = xs - w;   // exclusive warp offsets
        }
        __syncthreads();
        int incl = x + warp_sums[tid >> 5] + s_carry;
        int excl = incl - v;
        if (i < NN) { g_off[i] = excl; g_cursor[i] = excl; }
        __syncthreads();
        if (tid == 1023) s_carry = incl;
        __syncthreads();
    }
    if (tid == 0) g_off[NN] = s_carry;
}

// ---------------- fill CSR src lists ----------------
__global__ void fill_kernel() {
    int e = blockIdx.x * blockDim.x + threadIdx.x;
    if (e >= EE) return;
    int d = g_pos[EE + e];
    int p = atomicAdd(&g_cursor[d], 1);
    g_srcs[p] = g_pos[e];
}

// ---------------- x -> bf16 hi/lo split ----------------
__global__ void xsplit_kernel(const float* __restrict__ x) {
    int i = blockIdx.x * blockDim.x + threadIdx.x;
    if (i >= NN*DIN) return;
    __nv_bfloat16 hi, lo;
    split_bf16(x[i], hi, lo);
    g_xhi[i] = hi; g_xlo[i] = lo;
}

// ---------------- weights -> concat + split ----------------
__global__ void wsplit_kernel(const float* __restrict__ Wrel0, const float* __restrict__ Wroot0,
                              const float* __restrict__ Wrel1, const float* __restrict__ Wroot1) {
    int i = blockIdx.x * blockDim.x + threadIdx.x;
    if (i < DIN*256) {
        int k = i >> 8, n = i & 255;
        float w = (n < 128) ? Wrel0[k*128 + n] : Wroot0[k*128 + (n - 128)];
        __nv_bfloat16 hi, lo; split_bf16(w, hi, lo);
        g_B0hi[i] = hi; g_B0lo[i] = lo;
    } else if (i < DIN*256 + DHID*128) {
        int j = i - DIN*256;
        int k = j >> 7, n = j & 127;
        float w = (n < 64) ? Wrel1[k*64 + n] : Wroot1[k*64 + (n - 64)];
        __nv_bfloat16 hi, lo; split_bf16(w, hi, lo);
        g_B1hi[j] = hi; g_B1lo[j] = lo;
    }
}

// ---------------- WMMA split-precision GEMM: C[M,Nc] = A[M,128] @ B[128,Nc] ----------------
// 128x128 tile/block, 512 threads (16 warps 4x4), warp tile 32x32, K=128.
#define GLD 136
#define STG_LD 132
__global__ __launch_bounds__(512) void gemm_split_kernel(
    const __nv_bfloat16* __restrict__ Ahi_g, const __nv_bfloat16* __restrict__ Alo_g,
    const __nv_bfloat16* __restrict__ Bhi_g, const __nv_bfloat16* __restrict__ Blo_g,
    float* __restrict__ C, int M, int Nc)
{
    extern __shared__ char smraw[];
    __nv_bfloat16* Ahi = (__nv_bfloat16*)smraw;
    __nv_bfloat16* Alo = Ahi + 128 * GLD;
    __nv_bfloat16* Bhi = Alo + 128 * GLD;
    __nv_bfloat16* Blo = Bhi + 128 * GLD;

    int tid = threadIdx.x;
    int bi = blockIdx.y * 128, bc = blockIdx.x * 128;
    const int4 zero4 = make_int4(0, 0, 0, 0);

    for (int i = tid; i < 128 * 16; i += 512) {
        int r = i >> 4, c = (i & 15) * 8;
        int ar = bi + r;
        *(int4*)&Ahi[r * GLD + c] = (ar < M) ? *(const int4*)&Ahi_g[(size_t)ar * 128 + c] : zero4;
        *(int4*)&Alo[r * GLD + c] = (ar < M) ? *(const int4*)&Alo_g[(size_t)ar * 128 + c] : zero4;
        *(int4*)&Bhi[r * GLD + c] = *(const int4*)&Bhi_g[(size_t)r * Nc + bc + c];
        *(int4*)&Blo[r * GLD + c] = *(const int4*)&Blo_g[(size_t)r * Nc + bc + c];
    }
    __syncthreads();

    int warp = tid >> 5;
    int wm = (warp >> 2) * 32, wn = (warp & 3) * 32;

    wmma::fragment<wmma::accumulator, 16, 16, 16, float> acc[2][2];
    #pragma unroll
    for (int i = 0; i < 2; i++)
        #pragma unroll
        for (int j = 0; j < 2; j++) wmma::fill_fragment(acc[i][j], 0.f);

    #pragma unroll
    for (int k0 = 0; k0 < 8; k0++) {
        wmma::fragment<wmma::matrix_a, 16, 16, 16, __nv_bfloat16, wmma::row_major> ahi[2], alo[2];
        wmma::fragment<wmma::matrix_b, 16, 16, 16, __nv_bfloat16, wmma::row_major> bhi[2], blo[2];
        #pragma unroll
        for (int i = 0; i < 2; i++) {
            wmma::load_matrix_sync(ahi[i], &Ahi[(wm + i*16) * GLD + k0*16], GLD);
            wmma::load_matrix_sync(alo[i], &Alo[(wm + i*16) * GLD + k0*16], GLD);
        }
        #pragma unroll
        for (int j = 0; j < 2; j++) {
            wmma::load_matrix_sync(bhi[j], &Bhi[(k0*16) * GLD + wn + j*16], GLD);
            wmma::load_matrix_sync(blo[j], &Blo[(k0*16) * GLD + wn + j*16], GLD);
        }
        #pragma unroll
        for (int i = 0; i < 2; i++)
            #pragma unroll
            for (int j = 0; j < 2; j++) {
                wmma::mma_sync(acc[i][j], ahi[i], bhi[j], acc[i][j]);
                wmma::mma_sync(acc[i][j], ahi[i], blo[j], acc[i][j]);
                wmma::mma_sync(acc[i][j], alo[i], bhi[j], acc[i][j]);
            }
    }

    if (bi + 128 <= M) {
        #pragma unroll
        for (int i = 0; i < 2; i++)
            #pragma unroll
            for (int j = 0; j < 2; j++)
                wmma::store_matrix_sync(&C[(size_t)(bi + wm + i*16) * Nc + bc + wn + j*16],
                                        acc[i][j], Nc, wmma::mem_row_major);
    } else {
        __syncthreads();
        float* st = (float*)smraw;   // 128 x STG_LD floats
        #pragma unroll
        for (int i = 0; i < 2; i++)
            #pragma unroll
            for (int j = 0; j < 2; j++)
                wmma::store_matrix_sync(&st[(wm + i*16) * STG_LD + wn + j*16],
                                        acc[i][j], STG_LD, wmma::mem_row_major);
        __syncthreads();
        for (int i = tid; i < 128 * 128; i += 512) {
            int r = i >> 7, c = i & 127;
            if (bi + r < M)
                C[(size_t)(bi + r) * Nc + bc + c] = st[r * STG_LD + c];
        }
    }
}

// ---------------- gather0: agg + root + bias -> tanh -> bf16 split (h) ----------------
__global__ void gather0_kernel(const float* __restrict__ b0) {
    int n = (blockIdx.x * blockDim.x + threadIdx.x) >> 5;
    int l = threadIdx.x & 31;
    if (n >= NN) return;
    int beg = g_off[n], end = g_off[n+1];
    float4 acc = make_float4(0.f, 0.f, 0.f, 0.f);
    int e = beg;
    for (; e + 3 < end; e += 4) {
        int s0 = g_srcs[e], s1 = g_srcs[e+1], s2 = g_srcs[e+2], s3 = g_srcs[e+3];
        float4 v0 = *(const float4*)&g_y0[(size_t)s0 * 256 + l*4];
        float4 v1 = *(const float4*)&g_y0[(size_t)s1 * 256 + l*4];
        float4 v2 = *(const float4*)&g_y0[(size_t)s2 * 256 + l*4];
        float4 v3 = *(const float4*)&g_y0[(size_t)s3 * 256 + l*4];
        acc.x += v0.x + v1.x + v2.x + v3.x;
        acc.y += v0.y + v1.y + v2.y + v3.y;
        acc.z += v0.z + v1.z + v2.z + v3.z;
        acc.w += v0.w + v1.w + v2.w + v3.w;
    }
    for (; e < end; e++) {
        int s = g_srcs[e];
        float4 v = *(const float4*)&g_y0[(size_t)s * 256 + l*4];
        acc.x += v.x; acc.y += v.y; acc.z += v.z; acc.w += v.w;
    }
    float4 r  = *(const float4*)&g_y0[(size_t)n * 256 + 128 + l*4];
    float4 bb = *(const float4*)&b0[l*4];
    float h0 = tanhf(acc.x + r.x + bb.x);
    float h1 = tanhf(acc.y + r.y + bb.y);
    float h2 = tanhf(acc.z + r.z + bb.z);
    float h3 = tanhf(acc.w + r.w + bb.w);
    __nv_bfloat16 a0, a1, a2, a3, c0, c1, c2, c3;
    split_bf16(h0, a0, c0); split_bf16(h1, a1, c1);
    split_bf16(h2, a2, c2); split_bf16(h3, a3, c3);
    int base = n * DHID + l*4;
    *(__nv_bfloat162*)&g_hh0[base]     = __halves2bfloat162(a0, a1);
    *(__nv_bfloat162*)&g_hh0[base + 2] = __halves2bfloat162(a2, a3);
    *(__nv_bfloat162*)&g_hl0[base]     = __halves2bfloat162(c0, c1);
    *(__nv_bfloat162*)&g_hl0[base + 2] = __halves2bfloat162(c2, c3);
}

// ---------------- gather1: agg + root + bias -> h2, normalize -> bf16 split ----------------
__global__ void gather1_kernel(const float* __restrict__ b1) {
    int n = (blockIdx.x * blockDim.x + threadIdx.x) >> 5;
    int l = threadIdx.x & 31;
    if (n >= NN) return;
    int beg = g_off[n], end = g_off[n+1];
    float2 acc = make_float2(0.f, 0.f);
    int e = beg;
    for (; e + 3 < end; e += 4) {
        int s0 = g_srcs[e], s1 = g_srcs[e+1], s2 = g_srcs[e+2], s3 = g_srcs[e+3];
        float2 v0 = *(const float2*)&g_y1[(size_t)s0 * 128 + l*2];
        float2 v1 = *(const float2*)&g_y1[(size_t)s1 * 128 + l*2];
        float2 v2 = *(const float2*)&g_y1[(size_t)s2 * 128 + l*2];
        float2 v3 = *(const float2*)&g_y1[(size_t)s3 * 128 + l*2];
        acc.x += v0.x + v1.x + v2.x + v3.x;
        acc.y += v0.y + v1.y + v2.y + v3.y;
    }
    for (; e < end; e++) {
        int s = g_srcs[e];
        float2 v = *(const float2*)&g_y1[(size_t)s * 128 + l*2];
        acc.x += v.x; acc.y += v.y;
    }
    float2 r = *(const float2*)&g_y1[(size_t)n * 128 + 64 + l*2];
    float x0 = acc.x + r.x + b1[l*2];
    float x1 = acc.y + r.y + b1[l*2 + 1];
    float ss = x0*x0 + x1*x1;
    for (int off = 16; off; off >>= 1) ss += __shfl_xor_sync(0xffffffffu, ss, off);
    float inv = 1.f / fmaxf(sqrtf(ss), 1e-8f);
    int base = n * DOUT + l*2;
    *(float2*)&g_h2[base] = make_float2(x0, x1);
    float n0 = x0 * inv, n1 = x1 * inv;
    __nv_bfloat16 h0, h1, l0, l1;
    split_bf16(n0, h0, l0); split_bf16(n1, h1, l1);
    *(__nv_bfloat162*)&g_hhi[base] = __halves2bfloat162(h0, h1);
    *(__nv_bfloat162*)&g_hlo[base] = __halves2bfloat162(l0, l1);
}

// ---------------- BCE reconstruction loss ----------------
__global__ __launch_bounds__(512) void loss_kernel() {
    __shared__ float s_acc[2];
    if (threadIdx.x < 2) s_acc[threadIdx.x] = 0.f;
    __syncthreads();
    int gw = (blockIdx.x * blockDim.x + threadIdx.x) >> 5;
    int lane = threadIdx.x & 31;
    if (gw < 2*EE) {
        int isneg = (gw >= EE) ? 1 : 0;
        const int* ei = isneg ? g_neg : g_pos;
        int e = isneg ? gw - EE : gw;
        int s = ei[e], d = ei[EE + e];
        float2 a = *(const float2*)&g_h2[s * DOUT + lane * 2];
        float2 b = *(const float2*)&g_h2[d * DOUT + lane * 2];
        float dot = a.x*b.x + a.y*b.y;
        for (int off = 16; off; off >>= 1) dot += __shfl_xor_sync(0xffffffffu, dot, off);
        if (lane == 0) {
            float xx = isneg ? dot : -dot;
            float sp = (xx > 0.f) ? xx + log1pf(expf(-xx)) : log1pf(expf(xx));
            atomicAdd(&s_acc[isneg], sp);
        }
    }
    __syncthreads();
    if (threadIdx.x < 2) atomicAdd(&g_loss[threadIdx.x], s_acc[threadIdx.x]);
}

__global__ void write_loss_kernel(float* out) {
    out[(size_t)NN * NN] = g_loss[0] * (1.f / EE) + g_loss[1] * (1.f / EE);
}

// ---------------- sim = sigmoid(hn @ hn^T) via WMMA bf16 split-precision ----------------
#define LDA 72
__global__ __launch_bounds__(512) void sim_kernel(float* __restrict__ out) {
    extern __shared__ char smraw[];
    __nv_bfloat16* Ahi = (__nv_bfloat16*)smraw;
    __nv_bfloat16* Alo = Ahi + 128 * LDA;
    __nv_bfloat16* Bhi = Alo + 128 * LDA;
    __nv_bfloat16* Blo = Bhi + 128 * LDA;

    int tid = threadIdx.x;
    int bi = blockIdx.y * 128, bj = blockIdx.x * 128;

    for (int i = tid; i < 128 * 8; i += 512) {
        int r = i >> 3, c = (i & 7) * 8;
        *(int4*)&Ahi[r * LDA + c] = *(const int4*)&g_hhi[(size_t)(bi + r) * DOUT + c];
        *(int4*)&Alo[r * LDA + c] = *(const int4*)&g_hlo[(size_t)(bi + r) * DOUT + c];
        *(int4*)&Bhi[r * LDA + c] = *(const int4*)&g_hhi[(size_t)(bj + r) * DOUT + c];
        *(int4*)&Blo[r * LDA + c] = *(const int4*)&g_hlo[(size_t)(bj + r) * DOUT + c];
    }
    __syncthreads();

    int warp = tid >> 5;
    int wm = (warp >> 2) * 32, wn = (warp & 3) * 32;

    wmma::fragment<wmma::accumulator, 16, 16, 16, float> acc[2][2];
    #pragma unroll
    for (int i = 0; i < 2; i++)
        #pragma unroll
        for (int j = 0; j < 2; j++) wmma::fill_fragment(acc[i][j], 0.f);

    #pragma unroll
    for (int k0 = 0; k0 < 4; k0++) {
        wmma::fragment<wmma::matrix_a, 16, 16, 16, __nv_bfloat16, wmma::row_major> ahi[2], alo[2];
        wmma::fragment<wmma::matrix_b, 16, 16, 16, __nv_bfloat16, wmma::col_major> bhi[2], blo[2];
        #pragma unroll
        for (int i = 0; i < 2; i++) {
            wmma::load_matrix_sync(ahi[i], &Ahi[(wm + i*16) * LDA + k0*16], LDA);
            wmma::load_matrix_sync(alo[i], &Alo[(wm + i*16) * LDA + k0*16], LDA);
        }
        #pragma unroll
        for (int j = 0; j < 2; j++) {
            wmma::load_matrix_sync(bhi[j], &Bhi[(wn + j*16) * LDA + k0*16], LDA);
            wmma::load_matrix_sync(blo[j], &Blo[(wn + j*16) * LDA + k0*16], LDA);
        }
        #pragma unroll
        for (int i = 0; i < 2; i++)
            #pragma unroll
            for (int j = 0; j < 2; j++) {
                wmma::mma_sync(acc[i][j], ahi[i], bhi[j], acc[i][j]);
                wmma::mma_sync(acc[i][j], ahi[i], blo[j], acc[i][j]);
                wmma::mma_sync(acc[i][j], alo[i], bhi[j], acc[i][j]);
            }
    }

    #pragma unroll
    for (int i = 0; i < 2; i++)
        #pragma unroll
        for (int j = 0; j < 2; j++)
            #pragma unroll
            for (int e = 0; e < acc[i][j].num_elements; e++)
                acc[i][j].x[e] = sigmoid_poly(acc[i][j].x[e]);

    bool interior = (bi + 128 <= NN) && (bj + 128 <= NN);
    if (interior) {
        #pragma unroll
        for (int i = 0; i < 2; i++)
            #pragma unroll
            for (int j = 0; j < 2; j++)
                wmma::store_matrix_sync(&out[(size_t)(bi + wm + i*16) * NN + bj + wn + j*16],
                                        acc[i][j], NN, wmma::mem_row_major);
    } else {
        __syncthreads();
        float* st = (float*)smraw;   // 128 x STG_LD
        #pragma unroll
        for (int i = 0; i < 2; i++)
            #pragma unroll
            for (int j = 0; j < 2; j++)
                wmma::store_matrix_sync(&st[(wm + i*16) * STG_LD + wn + j*16],
                                        acc[i][j], STG_LD, wmma::mem_row_major);
        __syncthreads();
        for (int i = tid; i < 128 * 128; i += 512) {
            int r = i >> 7, c = i & 127;
            if (bi + r < NN && bj + c < NN)
                out[(size_t)(bi + r) * NN + bj + c] = st[r * STG_LD + c];
        }
    }
}

// ---------------- launcher ----------------
extern "C" void kernel_launch(void* const* d_in, const int* in_sizes, int n_in,
                              void* d_out, int out_size)
{
    const float* x      = (const float*)d_in[1];
    const void*  ei_raw = d_in[2];
    const void*  ne_raw = d_in[3];
    const float* Wrel0  = (const float*)d_in[4];
    const float* Wroot0 = (const float*)d_in[5];
    const float* b0     = (const float*)d_in[6];
    const float* Wrel1  = (const float*)d_in[7];
    const float* Wroot1 = (const float*)d_in[8];
    const float* b1     = (const float*)d_in[9];
    float* out = (float*)d_out;

    __nv_bfloat16 *xhi, *xlo, *B0hi, *B0lo, *B1hi, *B1lo, *hh0, *hl0;
    float *y0, *y1;
    cudaGetSymbolAddress((void**)&xhi,  g_xhi);
    cudaGetSymbolAddress((void**)&xlo,  g_xlo);
    cudaGetSymbolAddress((void**)&B0hi, g_B0hi);
    cudaGetSymbolAddress((void**)&B0lo, g_B0lo);
    cudaGetSymbolAddress((void**)&B1hi, g_B1hi);
    cudaGetSymbolAddress((void**)&B1lo, g_B1lo);
    cudaGetSymbolAddress((void**)&hh0,  g_hh0);
    cudaGetSymbolAddress((void**)&hl0,  g_hl0);
    cudaGetSymbolAddress((void**)&y0,   g_y0);
    cudaGetSymbolAddress((void**)&y1,   g_y1);

    const int smem_sim  = 4 * 128 * LDA * (int)sizeof(__nv_bfloat16);  // 73728
    const int smem_gemm = 4 * 128 * GLD * (int)sizeof(__nv_bfloat16);  // 139264
    cudaFuncSetAttribute(sim_kernel,  cudaFuncAttributeMaxDynamicSharedMemorySize, smem_sim);
    cudaFuncSetAttribute(gemm_split_kernel, cudaFuncAttributeMaxDynamicSharedMemorySize, smem_gemm);

    // edge normalize + CSR build
    detect_kernel<<<1, 32>>>(ei_raw);
    init_kernel<<<(NN + 255) / 256, 256>>>();
    convert_kernel<<<(2*EE + 255) / 256, 256>>>(ei_raw, ne_raw);
    scan_kernel<<<1, 1024>>>();
    fill_kernel<<<(EE + 255) / 256, 256>>>();

    // input / weight splits
    xsplit_kernel<<<(NN*DIN + 255) / 256, 256>>>(x);
    wsplit_kernel<<<(DIN*256 + DHID*128 + 255) / 256, 256>>>(Wrel0, Wroot0, Wrel1, Wroot1);

    // layer 0: y0 = x @ [Wrel0|Wroot0]; gather+tanh -> h (bf16 split)
    gemm_split_kernel<<<dim3(2, (NN + 127)/128), 512, smem_gemm>>>(xhi, xlo, B0hi, B0lo, y0, NN, 256);
    gather0_kernel<<<(NN*32 + 255) / 256, 256>>>(b0);

    // layer 1: y1 = h @ [Wrel1|Wroot1]; gather+finalize -> h2, hn split
    gemm_split_kernel<<<dim3(1, (NN + 127)/128), 512, smem_gemm>>>(hh0, hl0, B1hi, B1lo, y1, NN, 128);
    gather1_kernel<<<(NN*32 + 255) / 256, 256>>>(b1);

    // loss
    loss_kernel<<<(2*EE + 15) / 16, 512>>>();
    if ((long long)out_size > (long long)NN * NN)
        write_loss_kernel<<<1, 1>>>(out);

    // dense sigmoid(hn @ hn^T)
    dim3 simgrid((NN + 127) / 128, (NN + 127) / 128);
    sim_kernel<<<simgrid, 512, smem_sim>>>(out);
}

// round 8
// speedup vs baseline: 3.1607x; 1.1669x over previous
#include <cuda_runtime.h>
#include <cuda_bf16.h>
#include <mma.h>
#include <math.h>

using namespace nvcuda;

#define NN   10000
#define NPAD 10112          // 79 * 128
#define EE   320000
#define DIN  128
#define DHID 128
#define DOUT 64
#define NT   79             // number of 128-tiles
#define NTRI (NT*(NT+1)/2)  // 3160 upper-triangular tiles

// ---------------- scratch (static __device__ globals: allocation-free) ----------------
__device__ __nv_bfloat16 g_xhi[NN*DIN];     // bf16 hi/lo split of x
__device__ __nv_bfloat16 g_xlo[NN*DIN];
__device__ __nv_bfloat16 g_B0hi[DIN*256];   // [Wrel0 | Wroot0] split
__device__ __nv_bfloat16 g_B0lo[DIN*256];
__device__ __nv_bfloat16 g_B1hi[DHID*128];  // [Wrel1 | Wroot1] split
__device__ __nv_bfloat16 g_B1lo[DHID*128];
__device__ float g_y0 [NN*256];             // [x@Wrel0 | x@Wroot0]
__device__ float g_y1 [NN*128];             // [h@Wrel1 | h@Wroot1]
__device__ __nv_bfloat16 g_hh0[NN*DHID];    // split of h (layer-1 A input)
__device__ __nv_bfloat16 g_hl0[NN*DHID];
__device__ float g_h2 [NN*DOUT];            // final embeddings
__device__ __nv_bfloat16 g_hhi[NPAD*DOUT];  // split of normalized h (pad rows stay 0)
__device__ __nv_bfloat16 g_hlo[NPAD*DOUT];
__device__ int   g_pos  [2*EE];             // int32 edge indices (src | dst)
__device__ int   g_neg  [2*EE];
__device__ int   g_deg  [NN];               // CSR build
__device__ int   g_off  [NN+1];
__device__ int   g_cursor[NN];
__device__ int   g_srcs [EE];               // srcs grouped by dst
__device__ float g_loss [2];
__device__ int   g_is64;                    // edge index dtype flag

// ---------------- MUFU-free sigmoid for |x| <= ~1.01 ----------------
// sigmoid(x) = 0.5 + 0.5*tanh(x/2); odd Taylor of tanh to u^9, |u|<=0.5 -> err ~4e-6
__device__ __forceinline__ float sigmoid_poly(float x) {
    float u  = 0.5f * x;
    float u2 = u * u;
    float p = 2.1869488e-2f;
    p = fmaf(p, u2, -5.3968254e-2f);
    p = fmaf(p, u2,  1.3333334e-1f);
    p = fmaf(p, u2, -3.3333334e-1f);
    p = fmaf(p, u2,  1.0f);
    return fmaf(0.5f, u * p, 0.5f);
}

__device__ __forceinline__ void split_bf16(float v, __nv_bfloat16& hi, __nv_bfloat16& lo) {
    hi = __float2bfloat16(v);
    lo = __float2bfloat16(v - __bfloat162float(hi));
}

// ---------------- dtype detect ----------------
__global__ void detect_kernel(const void* p) {
    const unsigned* u = (const unsigned*)p;
    int lane = threadIdx.x & 31;
    int nz = 0;
    for (int i = lane; i < 64; i += 32) nz |= (u[2*i + 1] != 0u);
    for (int off = 16; off; off >>= 1) nz |= __shfl_xor_sync(0xffffffffu, nz, off);
    if (lane == 0) g_is64 = !nz;
}

// ---------------- zero deg + loss ----------------
__global__ void init_kernel() {
    int i = blockIdx.x * blockDim.x + threadIdx.x;
    if (i < NN) g_deg[i] = 0;
    if (i < 2)  g_loss[i] = 0.f;
}

// ---------------- edge convert + degree count ----------------
__global__ void convert_kernel(const void* p0, const void* p1) {
    int i = blockIdx.x * blockDim.x + threadIdx.x;
    if (i >= 2*EE) return;
    int vp, vn;
    if (g_is64) {
        vp = (int)((const long long*)p0)[i];
        vn = (int)((const long long*)p1)[i];
    } else {
        vp = ((const int*)p0)[i];
        vn = ((const int*)p1)[i];
    }
    g_pos[i] = vp;
    g_neg[i] = vn;
    if (i >= EE) atomicAdd(&g_deg[vp], 1);   // dst entries
}

// ---------------- exclusive scan of degrees (1 block) -- R5-proven version ----------------
__global__ __launch_bounds__(1024) void scan_kernel() {
    __shared__ int warp_sums[32];
    __shared__ int s_carry;
    int tid = threadIdx.x;
    if (tid == 0) s_carry = 0;
    __syncthreads();
    for (int base = 0; base < NN; base += 1024) {
        int i = base + tid;
        int v = (i < NN) ? g_deg[i] : 0;
        int x = v;
        #pragma unroll
        for (int off = 1; off < 32; off <<= 1) {
            int y = __shfl_up_sync(0xffffffffu, x, off);
            if ((tid & 31) >= off) x += y;
        }
        if ((tid & 31) == 31) warp_sums[tid >> 5] = x;
        __syncthreads();
        if (tid < 32) {
            int w = warp_sums[tid];
            int xs = w;
            #pragma unroll
            for (int off = 1; off < 32; off <<= 1) {
                int y = __shfl_up_sync(0xffffffffu, xs, off);
                if (tid >= off) xs += y;
            }
            warp_sums[tid] = xs - w;
        }
        __syncthreads();
        int incl = x + warp_sums[tid >> 5] + s_carry;
        int excl = incl - v;
        if (i < NN) { g_off[i] = excl; g_cursor[i] = excl; }
        __syncthreads();
        if (tid == 1023) s_carry = incl;
        __syncthreads();
    }
    if (tid == 0) g_off[NN] = s_carry;
}

// ---------------- fill CSR src lists ----------------
__global__ void fill_kernel() {
    int e = blockIdx.x * blockDim.x + threadIdx.x;
    if (e >= EE) return;
    int d = g_pos[EE + e];
    int p = atomicAdd(&g_cursor[d], 1);
    g_srcs[p] = g_pos[e];
}

// ---------------- x -> bf16 hi/lo split ----------------
__global__ void xsplit_kernel(const float* __restrict__ x) {
    int i = blockIdx.x * blockDim.x + threadIdx.x;
    if (i >= NN*DIN) return;
    __nv_bfloat16 hi, lo;
    split_bf16(x[i], hi, lo);
    g_xhi[i] = hi; g_xlo[i] = lo;
}

// ---------------- weights -> concat + split ----------------
__global__ void wsplit_kernel(const float* __restrict__ Wrel0, const float* __restrict__ Wroot0,
                              const float* __restrict__ Wrel1, const float* __restrict__ Wroot1) {
    int i = blockIdx.x * blockDim.x + threadIdx.x;
    if (i < DIN*256) {
        int k = i >> 8, n = i & 255;
        float w = (n < 128) ? Wrel0[k*128 + n] : Wroot0[k*128 + (n - 128)];
        __nv_bfloat16 hi, lo; split_bf16(w, hi, lo);
        g_B0hi[i] = hi; g_B0lo[i] = lo;
    } else if (i < DIN*256 + DHID*128) {
        int j = i - DIN*256;
        int k = j >> 7, n = j & 127;
        float w = (n < 64) ? Wrel1[k*64 + n] : Wroot1[k*64 + (n - 64)];
        __nv_bfloat16 hi, lo; split_bf16(w, hi, lo);
        g_B1hi[j] = hi; g_B1lo[j] = lo;
    }
}

// ---------------- WMMA split-precision GEMM: C[M,Nc] = A[M,128] @ B[128,Nc] ----------------
#define GLD 136
#define STG_LD 132
__global__ __launch_bounds__(512) void gemm_split_kernel(
    const __nv_bfloat16* __restrict__ Ahi_g, const __nv_bfloat16* __restrict__ Alo_g,
    const __nv_bfloat16* __restrict__ Bhi_g, const __nv_bfloat16* __restrict__ Blo_g,
    float* __restrict__ C, int M, int Nc)
{
    extern __shared__ char smraw[];
    __nv_bfloat16* Ahi = (__nv_bfloat16*)smraw;
    __nv_bfloat16* Alo = Ahi + 128 * GLD;
    __nv_bfloat16* Bhi = Alo + 128 * GLD;
    __nv_bfloat16* Blo = Bhi + 128 * GLD;

    int tid = threadIdx.x;
    int bi = blockIdx.y * 128, bc = blockIdx.x * 128;
    const int4 zero4 = make_int4(0, 0, 0, 0);

    for (int i = tid; i < 128 * 16; i += 512) {
        int r = i >> 4, c = (i & 15) * 8;
        int ar = bi + r;
        *(int4*)&Ahi[r * GLD + c] = (ar < M) ? *(const int4*)&Ahi_g[(size_t)ar * 128 + c] : zero4;
        *(int4*)&Alo[r * GLD + c] = (ar < M) ? *(const int4*)&Alo_g[(size_t)ar * 128 + c] : zero4;
        *(int4*)&Bhi[r * GLD + c] = *(const int4*)&Bhi_g[(size_t)r * Nc + bc + c];
        *(int4*)&Blo[r * GLD + c] = *(const int4*)&Blo_g[(size_t)r * Nc + bc + c];
    }
    __syncthreads();

    int warp = tid >> 5;
    int wm = (warp >> 2) * 32, wn = (warp & 3) * 32;

    wmma::fragment<wmma::accumulator, 16, 16, 16, float> acc[2][2];
    #pragma unroll
    for (int i = 0; i < 2; i++)
        #pragma unroll
        for (int j = 0; j < 2; j++) wmma::fill_fragment(acc[i][j], 0.f);

    #pragma unroll
    for (int k0 = 0; k0 < 8; k0++) {
        wmma::fragment<wmma::matrix_a, 16, 16, 16, __nv_bfloat16, wmma::row_major> ahi[2], alo[2];
        wmma::fragment<wmma::matrix_b, 16, 16, 16, __nv_bfloat16, wmma::row_major> bhi[2], blo[2];
        #pragma unroll
        for (int i = 0; i < 2; i++) {
            wmma::load_matrix_sync(ahi[i], &Ahi[(wm + i*16) * GLD + k0*16], GLD);
            wmma::load_matrix_sync(alo[i], &Alo[(wm + i*16) * GLD + k0*16], GLD);
        }
        #pragma unroll
        for (int j = 0; j < 2; j++) {
            wmma::load_matrix_sync(bhi[j], &Bhi[(k0*16) * GLD + wn + j*16], GLD);
            wmma::load_matrix_sync(blo[j], &Blo[(k0*16) * GLD + wn + j*16], GLD);
        }
        #pragma unroll
        for (int i = 0; i < 2; i++)
            #pragma unroll
            for (int j = 0; j < 2; j++) {
                wmma::mma_sync(acc[i][j], ahi[i], bhi[j], acc[i][j]);
                wmma::mma_sync(acc[i][j], ahi[i], blo[j], acc[i][j]);
                wmma::mma_sync(acc[i][j], alo[i], bhi[j], acc[i][j]);
            }
    }

    if (bi + 128 <= M) {
        #pragma unroll
        for (int i = 0; i < 2; i++)
            #pragma unroll
            for (int j = 0; j < 2; j++)
                wmma::store_matrix_sync(&C[(size_t)(bi + wm + i*16) * Nc + bc + wn + j*16],
                                        acc[i][j], Nc, wmma::mem_row_major);
    } else {
        __syncthreads();
        float* st = (float*)smraw;
        #pragma unroll
        for (int i = 0; i < 2; i++)
            #pragma unroll
            for (int j = 0; j < 2; j++)
                wmma::store_matrix_sync(&st[(wm + i*16) * STG_LD + wn + j*16],
                                        acc[i][j], STG_LD, wmma::mem_row_major);
        __syncthreads();
        for (int i = tid; i < 128 * 128; i += 512) {
            int r = i >> 7, c = i & 127;
            if (bi + r < M)
                C[(size_t)(bi + r) * Nc + bc + c] = st[r * STG_LD + c];
        }
    }
}

// ---------------- gather0: agg + root + bias -> tanh -> bf16 split (h) ----------------
__global__ void gather0_kernel(const float* __restrict__ b0) {
    int n = (blockIdx.x * blockDim.x + threadIdx.x) >> 5;
    int l = threadIdx.x & 31;
    if (n >= NN) return;
    int beg = g_off[n], end = g_off[n+1];
    float4 acc = make_float4(0.f, 0.f, 0.f, 0.f);
    int e = beg;
    for (; e + 3 < end; e += 4) {
        int s0 = g_srcs[e], s1 = g_srcs[e+1], s2 = g_srcs[e+2], s3 = g_srcs[e+3];
        float4 v0 = *(const float4*)&g_y0[(size_t)s0 * 256 + l*4];
        float4 v1 = *(const float4*)&g_y0[(size_t)s1 * 256 + l*4];
        float4 v2 = *(const float4*)&g_y0[(size_t)s2 * 256 + l*4];
        float4 v3 = *(const float4*)&g_y0[(size_t)s3 * 256 + l*4];
        acc.x += v0.x + v1.x + v2.x + v3.x;
        acc.y += v0.y + v1.y + v2.y + v3.y;
        acc.z += v0.z + v1.z + v2.z + v3.z;
        acc.w += v0.w + v1.w + v2.w + v3.w;
    }
    for (; e < end; e++) {
        int s = g_srcs[e];
        float4 v = *(const float4*)&g_y0[(size_t)s * 256 + l*4];
        acc.x += v.x; acc.y += v.y; acc.z += v.z; acc.w += v.w;
    }
    float4 r  = *(const float4*)&g_y0[(size_t)n * 256 + 128 + l*4];
    float4 bb = *(const float4*)&b0[l*4];
    float h0 = tanhf(acc.x + r.x + bb.x);
    float h1 = tanhf(acc.y + r.y + bb.y);
    float h2 = tanhf(acc.z + r.z + bb.z);
    float h3 = tanhf(acc.w + r.w + bb.w);
    __nv_bfloat16 a0, a1, a2, a3, c0, c1, c2, c3;
    split_bf16(h0, a0, c0); split_bf16(h1, a1, c1);
    split_bf16(h2, a2, c2); split_bf16(h3, a3, c3);
    int base = n * DHID + l*4;
    *(__nv_bfloat162*)&g_hh0[base]     = __halves2bfloat162(a0, a1);
    *(__nv_bfloat162*)&g_hh0[base + 2] = __halves2bfloat162(a2, a3);
    *(__nv_bfloat162*)&g_hl0[base]     = __halves2bfloat162(c0, c1);
    *(__nv_bfloat162*)&g_hl0[base + 2] = __halves2bfloat162(c2, c3);
}

// ---------------- gather1: agg + root + bias -> h2, normalize -> bf16 split ----------------
__global__ void gather1_kernel(const float* __restrict__ b1) {
    int n = (blockIdx.x * blockDim.x + threadIdx.x) >> 5;
    int l = threadIdx.x & 31;
    if (n >= NN) return;
    int beg = g_off[n], end = g_off[n+1];
    float2 acc = make_float2(0.f, 0.f);
    int e = beg;
    for (; e + 3 < end; e += 4) {
        int s0 = g_srcs[e], s1 = g_srcs[e+1], s2 = g_srcs[e+2], s3 = g_srcs[e+3];
        float2 v0 = *(const float2*)&g_y1[(size_t)s0 * 128 + l*2];
        float2 v1 = *(const float2*)&g_y1[(size_t)s1 * 128 + l*2];
        float2 v2 = *(const float2*)&g_y1[(size_t)s2 * 128 + l*2];
        float2 v3 = *(const float2*)&g_y1[(size_t)s3 * 128 + l*2];
        acc.x += v0.x + v1.x + v2.x + v3.x;
        acc.y += v0.y + v1.y + v2.y + v3.y;
    }
    for (; e < end; e++) {
        int s = g_srcs[e];
        float2 v = *(const float2*)&g_y1[(size_t)s * 128 + l*2];
        acc.x += v.x; acc.y += v.y;
    }
    float2 r = *(const float2*)&g_y1[(size_t)n * 128 + 64 + l*2];
    float x0 = acc.x + r.x + b1[l*2];
    float x1 = acc.y + r.y + b1[l*2 + 1];
    float ss = x0*x0 + x1*x1;
    for (int off = 16; off; off >>= 1) ss += __shfl_xor_sync(0xffffffffu, ss, off);
    float inv = 1.f / fmaxf(sqrtf(ss), 1e-8f);
    int base = n * DOUT + l*2;
    *(float2*)&g_h2[base] = make_float2(x0, x1);
    float n0 = x0 * inv, n1 = x1 * inv;
    __nv_bfloat16 h0, h1, l0, l1;
    split_bf16(n0, h0, l0); split_bf16(n1, h1, l1);
    *(__nv_bfloat162*)&g_hhi[base] = __halves2bfloat162(h0, h1);
    *(__nv_bfloat162*)&g_hlo[base] = __halves2bfloat162(l0, l1);
}

// ---------------- BCE reconstruction loss ----------------
__global__ __launch_bounds__(512) void loss_kernel() {
    __shared__ float s_acc[2];
    if (threadIdx.x < 2) s_acc[threadIdx.x] = 0.f;
    __syncthreads();
    int gw = (blockIdx.x * blockDim.x + threadIdx.x) >> 5;
    int lane = threadIdx.x & 31;
    if (gw < 2*EE) {
        int isneg = (gw >= EE) ? 1 : 0;
        const int* ei = isneg ? g_neg : g_pos;
        int e = isneg ? gw - EE : gw;
        int s = ei[e], d = ei[EE + e];
        float2 a = *(const float2*)&g_h2[s * DOUT + lane * 2];
        float2 b = *(const float2*)&g_h2[d * DOUT + lane * 2];
        float dot = a.x*b.x + a.y*b.y;
        for (int off = 16; off; off >>= 1) dot += __shfl_xor_sync(0xffffffffu, dot, off);
        if (lane == 0) {
            float xx = isneg ? dot : -dot;
            float sp = (xx > 0.f) ? xx + log1pf(expf(-xx)) : log1pf(expf(xx));
            atomicAdd(&s_acc[isneg], sp);
        }
    }
    __syncthreads();
    if (threadIdx.x < 2) atomicAdd(&g_loss[threadIdx.x], s_acc[threadIdx.x]);
}

__global__ void write_loss_kernel(float* out) {
    out[(size_t)NN * NN] = g_loss[0] * (1.f / EE) + g_loss[1] * (1.f / EE);
}

// ---------------- sim = sigmoid(hn @ hn^T), symmetric: triangular 1D grid ----------------
// Block b -> (ti, tj), ti<=tj, via bounded integer decode. Off-diagonal tiles
// mirrored with a col-major accumulator store (free C^T).
#define LDA 72
__global__ __launch_bounds__(512) void sim_kernel(float* __restrict__ out) {
    // exact integer decode: row ti has (NT - ti) tiles
    int b = blockIdx.x;
    int ti = 0;
    #pragma unroll 1
    while (b >= NT - ti) { b -= NT - ti; ti++; }   // <= 79 iterations, strictly decreasing b
    int tj = ti + b;

    extern __shared__ char smraw[];
    __nv_bfloat16* Ahi = (__nv_bfloat16*)smraw;
    __nv_bfloat16* Alo = Ahi + 128 * LDA;
    __nv_bfloat16* Bhi = Alo + 128 * LDA;
    __nv_bfloat16* Blo = Bhi + 128 * LDA;

    int tid = threadIdx.x;
    int bi = ti * 128, bj = tj * 128;

    for (int i = tid; i < 128 * 8; i += 512) {
        int r = i >> 3, c = (i & 7) * 8;
        *(int4*)&Ahi[r * LDA + c] = *(const int4*)&g_hhi[(size_t)(bi + r) * DOUT + c];
        *(int4*)&Alo[r * LDA + c] = *(const int4*)&g_hlo[(size_t)(bi + r) * DOUT + c];
        *(int4*)&Bhi[r * LDA + c] = *(const int4*)&g_hhi[(size_t)(bj + r) * DOUT + c];
        *(int4*)&Blo[r * LDA + c] = *(const int4*)&g_hlo[(size_t)(bj + r) * DOUT + c];
    }
    __syncthreads();

    int warp = tid >> 5;
    int wm = (warp >> 2) * 32, wn = (warp & 3) * 32;

    wmma::fragment<wmma::accumulator, 16, 16, 16, float> acc[2][2];
    #pragma unroll
    for (int i = 0; i < 2; i++)
        #pragma unroll
        for (int j = 0; j < 2; j++) wmma::fill_fragment(acc[i][j], 0.f);

    #pragma unroll
    for (int k0 = 0; k0 < 4; k0++) {
        wmma::fragment<wmma::matrix_a, 16, 16, 16, __nv_bfloat16, wmma::row_major> ahi[2], alo[2];
        wmma::fragment<wmma::matrix_b, 16, 16, 16, __nv_bfloat16, wmma::col_major> bhi[2], blo[2];
        #pragma unroll
        for (int i = 0; i < 2; i++) {
            wmma::load_matrix_sync(ahi[i], &Ahi[(wm + i*16) * LDA + k0*16], LDA);
            wmma::load_matrix_sync(alo[i], &Alo[(wm + i*16) * LDA + k0*16], LDA);
        }
        #pragma unroll
        for (int j = 0; j < 2; j++) {
            wmma::load_matrix_sync(bhi[j], &Bhi[(wn + j*16) * LDA + k0*16], LDA);
            wmma::load_matrix_sync(blo[j], &Blo[(wn + j*16) * LDA + k0*16], LDA);
        }
        #pragma unroll
        for (int i = 0; i < 2; i++)
            #pragma unroll
            for (int j = 0; j < 2; j++) {
                wmma::mma_sync(acc[i][j], ahi[i], bhi[j], acc[i][j]);
                wmma::mma_sync(acc[i][j], ahi[i], blo[j], acc[i][j]);
                wmma::mma_sync(acc[i][j], alo[i], bhi[j], acc[i][j]);
            }
    }

    #pragma unroll
    for (int i = 0; i < 2; i++)
        #pragma unroll
        for (int j = 0; j < 2; j++)
            #pragma unroll
            for (int e = 0; e < acc[i][j].num_elements; e++)
                acc[i][j].x[e] = sigmoid_poly(acc[i][j].x[e]);

    bool interior = (bj + 128 <= NN);   // only tj==NT-1 is edge; ti<=tj so bi-edge implies bj-edge
    float* st = (float*)smraw;          // 128 x STG_LD floats (reuses tile smem)

    // ---- direct tile [bi, bj] ----
    if (interior) {
        #pragma unroll
        for (int i = 0; i < 2; i++)
            #pragma unroll
            for (int j = 0; j < 2; j++)
                wmma::store_matrix_sync(&out[(size_t)(bi + wm + i*16) * NN + bj + wn + j*16],
                                        acc[i][j], NN, wmma::mem_row_major);
    } else {
        __syncthreads();
        #pragma unroll
        for (int i = 0; i < 2; i++)
            #pragma unroll
            for (int j = 0; j < 2; j++)
                wmma::store_matrix_sync(&st[(wm + i*16) * STG_LD + wn + j*16],
                                        acc[i][j], STG_LD, wmma::mem_row_major);
        __syncthreads();
        for (int i = tid; i < 128 * 128; i += 512) {
            int r = i >> 7, c = i & 127;
            if (bi + r < NN && bj + c < NN)
                out[(size_t)(bi + r) * NN + bj + c] = st[r * STG_LD + c];
        }
    }

    // ---- mirrored tile [bj, bi] = C^T ----
    if (ti != tj) {
        if (interior) {
            // col-major store of C == row-major store of C^T at the mirrored origin
            #pragma unroll
            for (int i = 0; i < 2; i++)
                #pragma unroll
                for (int j = 0; j < 2; j++)
                    wmma::store_matrix_sync(&out[(size_t)(bj + wn + j*16) * NN + bi + wm + i*16],
                                            acc[i][j], NN, wmma::mem_col_major);
        } else {
            // edge path (tj == NT-1): st holds C from the staged branch above
            for (int i = tid; i < 128 * 128; i += 512) {
                int r = i >> 7, c = i & 127;            // mirrored row bj+r, col bi+c
                if (bj + r < NN && bi + c < NN)
                    out[(size_t)(bj + r) * NN + bi + c] = st[c * STG_LD + r];
            }
        }
    }
}

// ---------------- launcher ----------------
extern "C" void kernel_launch(void* const* d_in, const int* in_sizes, int n_in,
                              void* d_out, int out_size)
{
    const float* x      = (const float*)d_in[1];
    const void*  ei_raw = d_in[2];
    const void*  ne_raw = d_in[3];
    const float* Wrel0  = (const float*)d_in[4];
    const float* Wroot0 = (const float*)d_in[5];
    const float* b0     = (const float*)d_in[6];
    const float* Wrel1  = (const float*)d_in[7];
    const float* Wroot1 = (const float*)d_in[8];
    const float* b1     = (const float*)d_in[9];
    float* out = (float*)d_out;

    __nv_bfloat16 *xhi, *xlo, *B0hi, *B0lo, *B1hi, *B1lo, *hh0, *hl0;
    float *y0, *y1;
    cudaGetSymbolAddress((void**)&xhi,  g_xhi);
    cudaGetSymbolAddress((void**)&xlo,  g_xlo);
    cudaGetSymbolAddress((void**)&B0hi, g_B0hi);
    cudaGetSymbolAddress((void**)&B0lo, g_B0lo);
    cudaGetSymbolAddress((void**)&B1hi, g_B1hi);
    cudaGetSymbolAddress((void**)&B1lo, g_B1lo);
    cudaGetSymbolAddress((void**)&hh0,  g_hh0);
    cudaGetSymbolAddress((void**)&hl0,  g_hl0);
    cudaGetSymbolAddress((void**)&y0,   g_y0);
    cudaGetSymbolAddress((void**)&y1,   g_y1);

    const int smem_sim  = 4 * 128 * LDA * (int)sizeof(__nv_bfloat16);  // 73728
    const int smem_gemm = 4 * 128 * GLD * (int)sizeof(__nv_bfloat16);  // 139264
    cudaFuncSetAttribute(sim_kernel,  cudaFuncAttributeMaxDynamicSharedMemorySize, smem_sim);
    cudaFuncSetAttribute(gemm_split_kernel, cudaFuncAttributeMaxDynamicSharedMemorySize, smem_gemm);

    // edge normalize + CSR build (R5-proven path)
    detect_kernel<<<1, 32>>>(ei_raw);
    init_kernel<<<(NN + 255) / 256, 256>>>();
    convert_kernel<<<(2*EE + 255) / 256, 256>>>(ei_raw, ne_raw);
    scan_kernel<<<1, 1024>>>();
    fill_kernel<<<(EE + 255) / 256, 256>>>();

    // input / weight splits
    xsplit_kernel<<<(NN*DIN + 255) / 256, 256>>>(x);
    wsplit_kernel<<<(DIN*256 + DHID*128 + 255) / 256, 256>>>(Wrel0, Wroot0, Wrel1, Wroot1);

    // layer 0: y0 = x @ [Wrel0|Wroot0]; gather+tanh -> h (bf16 split)
    gemm_split_kernel<<<dim3(2, (NN + 127)/128), 512, smem_gemm>>>(xhi, xlo, B0hi, B0lo, y0, NN, 256);
    gather0_kernel<<<(NN*32 + 255) / 256, 256>>>(b0);

    // layer 1: y1 = h @ [Wrel1|Wroot1]; gather+finalize -> h2, hn split
    gemm_split_kernel<<<dim3(1, (NN + 127)/128), 512, smem_gemm>>>(hh0, hl0, B1hi, B1lo, y1, NN, 128);
    gather1_kernel<<<(NN*32 + 255) / 256, 256>>>(b1);

    // loss
    loss_kernel<<<(2*EE + 15) / 16, 512>>>();
    if ((long long)out_size > (long long)NN * NN)
        write_loss_kernel<<<1, 1>>>(out);

    // dense sigmoid(hn @ hn^T), symmetric triangular grid
    sim_kernel<<<NTRI, 512, smem_sim>>>(out);
}